// round 13
// baseline (speedup 1.0000x reference)
#include <cuda_runtime.h>
#include <cuda_fp16.h>
#include <cstdint>

#define NN 100000
#define EE 1600000
#define DD 64

// ---- persistent scratch (device globals; no runtime allocation) ----
__device__ int    g_cnt[NN];          // in-degree histogram (edges only)
__device__ int    g_rowptr[NN + 1];   // CSR row pointers (by dst)
__device__ int    g_cursor[NN];       // scatter cursors (init = rowptr)
__device__ float  g_dis[NN];          // deg^{-1/2} (deg includes self-loop)
__device__ int    g_col[EE];          // CSR column = src node
__device__ int    g_state[128];       // decoupled-lookback state (memset 0)
__device__ __half g_hx[(size_t)NN * DD];  // pre-scaled fp16 activations X' = dis.*X
__device__ __half g_hy[(size_t)NN * DD];  // aggregated rows A = dn*S (GEMM input)

// ---------------------------------------------------------------------------
__global__ void hist_k(const int* __restrict__ dst, int e) {
    int i = blockIdx.x * blockDim.x + threadIdx.x;
    if (i < e) atomicAdd(&g_cnt[dst[i]], 1);
}

// Single-pass scan with decoupled lookback; also dis = rsqrt(deg+1) and
// prescale g_hx = half(dis .* x).
__global__ void scan_all_k(const float* __restrict__ x, int n) {
    __shared__ int   wsum[32];
    __shared__ int   s_agg;
    __shared__ int   s_excl;
    __shared__ float s_dis[1024];

    const int tid = threadIdx.x, lane = tid & 31, wid = tid >> 5;
    const int b = blockIdx.x;
    const int base = b * 1024;
    const int i = base + tid;

    int v = (i < n) ? g_cnt[i] : 0;
    float di = rsqrtf((float)(v + 1));
    if (i < n) g_dis[i] = di;
    s_dis[tid] = di;

    int xv = v;
    #pragma unroll
    for (int o = 1; o < 32; o <<= 1) {
        int y = __shfl_up_sync(0xffffffffu, xv, o);
        if (lane >= o) xv += y;
    }
    if (lane == 31) wsum[wid] = xv;
    __syncthreads();
    if (wid == 0) {
        int s = wsum[lane], t = s;
        #pragma unroll
        for (int o = 1; o < 32; o <<= 1) {
            int y = __shfl_up_sync(0xffffffffu, t, o);
            if (lane >= o) t += y;
        }
        wsum[lane] = t - s;
    }
    __syncthreads();
    int incl = xv + wsum[wid];
    if (tid == 1023) s_agg = incl;
    __syncthreads();
    int agg = s_agg;

    if (b == 0) {
        if (tid == 0) { atomicExch(&g_state[0], (agg << 2) | 2); s_excl = 0; }
    } else {
        if (tid == 0) atomicExch(&g_state[b], (agg << 2) | 1);
        if (wid == 0) {
            int excl = 0;
            int pb = b - 1;
            while (pb >= 0) {
                int idx = pb - lane;
                int s = (idx >= 0) ? atomicAdd(&g_state[idx], 0) : ((0 << 2) | 2);
                int st = s & 3, val = s >> 2;
                unsigned ready = __ballot_sync(0xffffffffu, st != 0);
                if (ready != 0xffffffffu) continue;
                unsigned has2 = __ballot_sync(0xffffffffu, st == 2);
                int contrib;
                if (has2) {
                    int first = __ffs(has2) - 1;
                    contrib = (lane <= first) ? val : 0;
                } else {
                    contrib = val;
                }
                #pragma unroll
                for (int o = 16; o > 0; o >>= 1)
                    contrib += __shfl_xor_sync(0xffffffffu, contrib, o);
                excl += contrib;
                if (has2) break;
                pb -= 32;
            }
            if (lane == 0) {
                atomicExch(&g_state[b], ((excl + agg) << 2) | 2);
                s_excl = excl;
            }
        }
    }
    __syncthreads();
    int excl = s_excl;

    if (i == 0) { g_rowptr[0] = 0; g_cursor[0] = 0; }
    if (i < n) {
        int fin = incl + excl;
        g_rowptr[i + 1] = fin;
        if (i + 1 < n) g_cursor[i + 1] = fin;
    }
    __syncthreads();

    for (int off = tid; off < 1024 * 32; off += 1024) {
        int row = base + (off >> 5);
        if (row >= n) break;
        int part = off & 31;
        float d = s_dis[row - base];
        float2 vv = reinterpret_cast<const float2*>(x + (size_t)row * DD)[part];
        reinterpret_cast<__half2*>(g_hx + (size_t)row * DD)[part] =
            __floats2half2_rn(d * vv.x, d * vv.y);
    }
}

__global__ void scat_k(const int* __restrict__ src, const int* __restrict__ dst, int e) {
    int i = blockIdx.x * blockDim.x + threadIdx.x;
    if (i < e) {
        int d = dst[i];
        int pos = atomicAdd(&g_cursor[d], 1);
        g_col[pos] = src[i];
    }
}

// ---------------------------------------------------------------------------
// Aggregation v5: v2's memory pattern + packed HADD2 + divergent trip counts.
// One warp per node; lane group g=lane>>3 walks edges j=start+g, j+=4 while
// j<end (loop condition IS the validity test — no predication instructions).
// sub=lane&7 owns 16B of the row; 4 half2 accumulators; single fp16->fp32
// conversion + fp32 cross-group reduction in the epilogue.
__global__ void __launch_bounds__(256) agg_k(int n) {
    const int lane = threadIdx.x & 31;
    const int node = (blockIdx.x * blockDim.x + threadIdx.x) >> 5;
    if (node >= n) return;
    const int group = lane >> 3, sub = lane & 7;

    __half2 h0 = __float2half2_rn(0.f), h1 = h0, h2 = h0, h3 = h0;

    const int end = g_rowptr[node + 1];
    for (int j = g_rowptr[node] + group; j < end; j += 4) {
        int c = g_col[j];
        uint4 v = *reinterpret_cast<const uint4*>(g_hx + (size_t)c * DD + sub * 8);
        const __half2* h = reinterpret_cast<const __half2*>(&v);
        h0 = __hadd2(h0, h[0]);
        h1 = __hadd2(h1, h[1]);
        h2 = __hadd2(h2, h[2]);
        h3 = __hadd2(h3, h[3]);
    }

    // epilogue: fp16 -> fp32 once, self term (group 0), fp32 reduce, store
    float fx[8];
    {
        float2 f;
        f = __half22float2(h0); fx[0] = f.x; fx[1] = f.y;
        f = __half22float2(h1); fx[2] = f.x; fx[3] = f.y;
        f = __half22float2(h2); fx[4] = f.x; fx[5] = f.y;
        f = __half22float2(h3); fx[6] = f.x; fx[7] = f.y;
    }
    if (group == 0) {                          // self term: bare X'[n]
        uint4 sv = *reinterpret_cast<const uint4*>(g_hx + (size_t)node * DD + sub * 8);
        const __half2* h = reinterpret_cast<const __half2*>(&sv);
        #pragma unroll
        for (int q = 0; q < 4; q++) {
            float2 f = __half22float2(h[q]);
            fx[2 * q] += f.x; fx[2 * q + 1] += f.y;
        }
    }

    #pragma unroll
    for (int q = 0; q < 8; q++) {
        fx[q] += __shfl_xor_sync(0xffffffffu, fx[q], 8);
        fx[q] += __shfl_xor_sync(0xffffffffu, fx[q], 16);
    }

    if (group == 0) {
        const float dn = g_dis[node];
        __half2 o[4];
        #pragma unroll
        for (int q = 0; q < 4; q++)
            o[q] = __floats2half2_rn(dn * fx[2 * q], dn * fx[2 * q + 1]);
        *reinterpret_cast<uint4*>(g_hy + (size_t)node * DD + sub * 8) =
            *reinterpret_cast<const uint4*>(o);
    }
}

// ---------------------------------------------------------------------------
// Persistent HMMA GEMM (unchanged): 148 blocks x 512 thr; W loaded once per
// block, grid-stride over 256-row tiles.
#define WT_STRIDE 72
#define GEMM_BLOCKS 148
__global__ void __launch_bounds__(512, 1)
gemm_k(const float* __restrict__ W, const float* __restrict__ bias,
       float* __restrict__ dout, int last, int n) {
    __shared__ __half Wt[64 * WT_STRIDE];    // Wt[n][k] = W[k][n]
    const int tid = threadIdx.x;
    for (int idx = tid; idx < 64 * 64; idx += 512) {
        int nn_ = idx >> 6, kk = idx & 63;
        Wt[nn_ * WT_STRIDE + kk] = __float2half(W[kk * 64 + nn_]);
    }
    __syncthreads();

    const int warp = tid >> 5, lane = tid & 31;
    const int g = lane >> 2, tk = lane & 3;
    const int ntiles = (n + 255) >> 8;

    for (int t = blockIdx.x; t < ntiles; t += gridDim.x) {
        const int base = t * 256 + warp * 16;
        const int r0 = base + g, r1 = r0 + 8;
        const bool p0 = r0 < n, p1 = r1 < n;

        uint32_t a[4][4];
        #pragma unroll
        for (int kt = 0; kt < 4; kt++) {
            int c0 = kt * 16 + tk * 2;
            a[kt][0] = p0 ? *reinterpret_cast<const uint32_t*>(g_hy + (size_t)r0 * DD + c0) : 0u;
            a[kt][1] = p1 ? *reinterpret_cast<const uint32_t*>(g_hy + (size_t)r1 * DD + c0) : 0u;
            a[kt][2] = p0 ? *reinterpret_cast<const uint32_t*>(g_hy + (size_t)r0 * DD + c0 + 8) : 0u;
            a[kt][3] = p1 ? *reinterpret_cast<const uint32_t*>(g_hy + (size_t)r1 * DD + c0 + 8) : 0u;
        }
        const float dn0 = p0 ? g_dis[r0] : 0.f;
        const float dn1 = p1 ? g_dis[r1] : 0.f;

        #pragma unroll
        for (int nt = 0; nt < 8; nt++) {
            float d0 = 0.f, d1 = 0.f, d2 = 0.f, d3 = 0.f;
            #pragma unroll
            for (int kt = 0; kt < 4; kt++) {
                const __half* bp = &Wt[(nt * 8 + g) * WT_STRIDE + kt * 16 + tk * 2];
                uint32_t b0 = *reinterpret_cast<const uint32_t*>(bp);
                uint32_t b1 = *reinterpret_cast<const uint32_t*>(bp + 8);
                asm volatile(
                    "mma.sync.aligned.m16n8k16.row.col.f32.f16.f16.f32 "
                    "{%0,%1,%2,%3}, {%4,%5,%6,%7}, {%8,%9}, {%0,%1,%2,%3};"
                    : "+f"(d0), "+f"(d1), "+f"(d2), "+f"(d3)
                    : "r"(a[kt][0]), "r"(a[kt][1]), "r"(a[kt][2]), "r"(a[kt][3]),
                      "r"(b0), "r"(b1));
            }
            int col = nt * 8 + tk * 2;
            float2 bv = *reinterpret_cast<const float2*>(bias + col);
            float y00 = d0 + bv.x, y01 = d1 + bv.y;
            float y10 = d2 + bv.x, y11 = d3 + bv.y;
            if (last) {
                if (p0) *reinterpret_cast<float2*>(dout + (size_t)r0 * DD + col) = make_float2(y00, y01);
                if (p1) *reinterpret_cast<float2*>(dout + (size_t)r1 * DD + col) = make_float2(y10, y11);
            } else {
                if (p0) *reinterpret_cast<__half2*>(g_hx + (size_t)r0 * DD + col) =
                            __floats2half2_rn(dn0 * y00, dn0 * y01);
                if (p1) *reinterpret_cast<__half2*>(g_hx + (size_t)r1 * DD + col) =
                            __floats2half2_rn(dn1 * y10, dn1 * y11);
            }
        }
    }
}

// ---------------------------------------------------------------------------
extern "C" void kernel_launch(void* const* d_in, const int* in_sizes, int n_in,
                              void* d_out, int out_size) {
    const float* x  = (const float*)d_in[0];
    const int*   ei = (const int*)d_in[1];
    const float* W[3] = { (const float*)d_in[2], (const float*)d_in[4], (const float*)d_in[6] };
    const float* B[3] = { (const float*)d_in[3], (const float*)d_in[5], (const float*)d_in[7] };

    int n = in_sizes[0] / DD; if (n > NN) n = NN;
    int e = in_sizes[1] / 2;  if (e > EE) e = EE;
    const int* src = ei;
    const int* dst = ei + e;

    void* p = nullptr;
    cudaGetSymbolAddress(&p, g_cnt);
    cudaMemsetAsync(p, 0, (size_t)n * sizeof(int));
    cudaGetSymbolAddress(&p, g_state);
    cudaMemsetAsync(p, 0, 128 * sizeof(int));

    int nb = (n + 1023) / 1024;
    hist_k    <<<(e + 255) / 256, 256>>>(dst, e);      // kernel 1
    scan_all_k<<<nb, 1024>>>(x, n);                    // kernel 2
    scat_k    <<<(e + 255) / 256, 256>>>(src, dst, e); // kernel 3

    const int agg_grid = (n * 32 + 255) / 256;         // one warp per node

    agg_k <<<agg_grid, 256>>>(n);                      // kernel 4 <- profiled
    gemm_k<<<GEMM_BLOCKS, 512>>>(W[0], B[0], nullptr, 0, n);
    agg_k <<<agg_grid, 256>>>(n);
    gemm_k<<<GEMM_BLOCKS, 512>>>(W[1], B[1], nullptr, 0, n);
    agg_k <<<agg_grid, 256>>>(n);
    gemm_k<<<GEMM_BLOCKS, 512>>>(W[2], B[2], (float*)d_out, 1, n);
}

// round 14
// speedup vs baseline: 1.1232x; 1.1232x over previous
#include <cuda_runtime.h>
#include <cuda_fp16.h>
#include <cstdint>

#define NN 100000
#define EE 1600000
#define DD 64

// ---- persistent scratch (device globals; no runtime allocation) ----
__device__ int    g_cnt[NN];          // in-degree histogram (edges only)
__device__ int    g_rowptr[NN + 1];   // CSR row pointers (by dst)
__device__ int    g_cursor[NN];       // scatter cursors (init = rowptr)
__device__ float  g_dis[NN];          // deg^{-1/2} (deg includes self-loop)
__device__ int    g_col[EE];          // CSR column = src node
__device__ int    g_state[128];       // decoupled-lookback state (memset 0)
__device__ __half g_hx[(size_t)NN * DD];  // pre-scaled fp16 activations X' = dis.*X
__device__ __half g_hy[(size_t)NN * DD];  // aggregated rows A = dn*S (GEMM input)

// ---------------------------------------------------------------------------
__global__ void hist_k(const int* __restrict__ dst, int e) {
    int i = blockIdx.x * blockDim.x + threadIdx.x;
    if (i < e) atomicAdd(&g_cnt[dst[i]], 1);
}

// Single-pass scan with decoupled lookback; also dis = rsqrt(deg+1) and
// prescale g_hx = half(dis .* x).
__global__ void scan_all_k(const float* __restrict__ x, int n) {
    __shared__ int   wsum[32];
    __shared__ int   s_agg;
    __shared__ int   s_excl;
    __shared__ float s_dis[1024];

    const int tid = threadIdx.x, lane = tid & 31, wid = tid >> 5;
    const int b = blockIdx.x;
    const int base = b * 1024;
    const int i = base + tid;

    int v = (i < n) ? g_cnt[i] : 0;
    float di = rsqrtf((float)(v + 1));
    if (i < n) g_dis[i] = di;
    s_dis[tid] = di;

    int xv = v;
    #pragma unroll
    for (int o = 1; o < 32; o <<= 1) {
        int y = __shfl_up_sync(0xffffffffu, xv, o);
        if (lane >= o) xv += y;
    }
    if (lane == 31) wsum[wid] = xv;
    __syncthreads();
    if (wid == 0) {
        int s = wsum[lane], t = s;
        #pragma unroll
        for (int o = 1; o < 32; o <<= 1) {
            int y = __shfl_up_sync(0xffffffffu, t, o);
            if (lane >= o) t += y;
        }
        wsum[lane] = t - s;
    }
    __syncthreads();
    int incl = xv + wsum[wid];
    if (tid == 1023) s_agg = incl;
    __syncthreads();
    int agg = s_agg;

    if (b == 0) {
        if (tid == 0) { atomicExch(&g_state[0], (agg << 2) | 2); s_excl = 0; }
    } else {
        if (tid == 0) atomicExch(&g_state[b], (agg << 2) | 1);
        if (wid == 0) {
            int excl = 0;
            int pb = b - 1;
            while (pb >= 0) {
                int idx = pb - lane;
                int s = (idx >= 0) ? atomicAdd(&g_state[idx], 0) : ((0 << 2) | 2);
                int st = s & 3, val = s >> 2;
                unsigned ready = __ballot_sync(0xffffffffu, st != 0);
                if (ready != 0xffffffffu) continue;
                unsigned has2 = __ballot_sync(0xffffffffu, st == 2);
                int contrib;
                if (has2) {
                    int first = __ffs(has2) - 1;
                    contrib = (lane <= first) ? val : 0;
                } else {
                    contrib = val;
                }
                #pragma unroll
                for (int o = 16; o > 0; o >>= 1)
                    contrib += __shfl_xor_sync(0xffffffffu, contrib, o);
                excl += contrib;
                if (has2) break;
                pb -= 32;
            }
            if (lane == 0) {
                atomicExch(&g_state[b], ((excl + agg) << 2) | 2);
                s_excl = excl;
            }
        }
    }
    __syncthreads();
    int excl = s_excl;

    if (i == 0) { g_rowptr[0] = 0; g_cursor[0] = 0; }
    if (i < n) {
        int fin = incl + excl;
        g_rowptr[i + 1] = fin;
        if (i + 1 < n) g_cursor[i + 1] = fin;
    }
    __syncthreads();

    for (int off = tid; off < 1024 * 32; off += 1024) {
        int row = base + (off >> 5);
        if (row >= n) break;
        int part = off & 31;
        float d = s_dis[row - base];
        float2 vv = reinterpret_cast<const float2*>(x + (size_t)row * DD)[part];
        reinterpret_cast<__half2*>(g_hx + (size_t)row * DD)[part] =
            __floats2half2_rn(d * vv.x, d * vv.y);
    }
}

__global__ void scat_k(const int* __restrict__ src, const int* __restrict__ dst, int e) {
    int i = blockIdx.x * blockDim.x + threadIdx.x;
    if (i < e) {
        int d = dst[i];
        int pos = atomicAdd(&g_cursor[d], 1);
        g_col[pos] = src[i];
    }
}

// ---------------------------------------------------------------------------
// Aggregation v6: v2's exact loop skeleton (predicated 4-edge unroll, no
// divergent trip counts) + packed HADD2 accumulation + launch_bounds to pin
// occupancy at 8 blocks/SM. One warp per node; lane group g=lane>>3 owns edge
// j+g, sub=lane&7 owns 16B of the row. Single fp16->fp32 conversion + fp32
// cross-group reduction in the epilogue.
__global__ void __launch_bounds__(256, 8) agg_k(int n) {
    const int lane = threadIdx.x & 31;
    const int node = (blockIdx.x * blockDim.x + threadIdx.x) >> 5;
    if (node >= n) return;
    const int group = lane >> 3, sub = lane & 7;

    __half2 h0 = __float2half2_rn(0.f), h1 = h0, h2 = h0, h3 = h0;

    int j = g_rowptr[node];
    const int end = g_rowptr[node + 1];
    for (; j < end; j += 4) {
        bool val = (j + group) < end;
        int c = val ? g_col[j + group] : node;     // safe address when invalid
        uint4 v = *reinterpret_cast<const uint4*>(g_hx + (size_t)c * DD + sub * 8);
        if (val) {                                  // predicated HADD2s
            const __half2* h = reinterpret_cast<const __half2*>(&v);
            h0 = __hadd2(h0, h[0]);
            h1 = __hadd2(h1, h[1]);
            h2 = __hadd2(h2, h[2]);
            h3 = __hadd2(h3, h[3]);
        }
    }

    // epilogue: fp16 -> fp32 once, self term (group 0), fp32 reduce, store
    float fx[8];
    {
        float2 f;
        f = __half22float2(h0); fx[0] = f.x; fx[1] = f.y;
        f = __half22float2(h1); fx[2] = f.x; fx[3] = f.y;
        f = __half22float2(h2); fx[4] = f.x; fx[5] = f.y;
        f = __half22float2(h3); fx[6] = f.x; fx[7] = f.y;
    }
    if (group == 0) {                               // self term: bare X'[n]
        uint4 sv = *reinterpret_cast<const uint4*>(g_hx + (size_t)node * DD + sub * 8);
        const __half2* h = reinterpret_cast<const __half2*>(&sv);
        #pragma unroll
        for (int q = 0; q < 4; q++) {
            float2 f = __half22float2(h[q]);
            fx[2 * q] += f.x; fx[2 * q + 1] += f.y;
        }
    }

    #pragma unroll
    for (int q = 0; q < 8; q++) {
        fx[q] += __shfl_xor_sync(0xffffffffu, fx[q], 8);
        fx[q] += __shfl_xor_sync(0xffffffffu, fx[q], 16);
    }

    if (group == 0) {
        const float dn = g_dis[node];
        __half2 o[4];
        #pragma unroll
        for (int q = 0; q < 4; q++)
            o[q] = __floats2half2_rn(dn * fx[2 * q], dn * fx[2 * q + 1]);
        *reinterpret_cast<uint4*>(g_hy + (size_t)node * DD + sub * 8) =
            *reinterpret_cast<const uint4*>(o);
    }
}

// ---------------------------------------------------------------------------
// Persistent HMMA GEMM (unchanged): 148 blocks x 512 thr; W loaded once per
// block, grid-stride over 256-row tiles.
#define WT_STRIDE 72
#define GEMM_BLOCKS 148
__global__ void __launch_bounds__(512, 1)
gemm_k(const float* __restrict__ W, const float* __restrict__ bias,
       float* __restrict__ dout, int last, int n) {
    __shared__ __half Wt[64 * WT_STRIDE];    // Wt[n][k] = W[k][n]
    const int tid = threadIdx.x;
    for (int idx = tid; idx < 64 * 64; idx += 512) {
        int nn_ = idx >> 6, kk = idx & 63;
        Wt[nn_ * WT_STRIDE + kk] = __float2half(W[kk * 64 + nn_]);
    }
    __syncthreads();

    const int warp = tid >> 5, lane = tid & 31;
    const int g = lane >> 2, tk = lane & 3;
    const int ntiles = (n + 255) >> 8;

    for (int t = blockIdx.x; t < ntiles; t += gridDim.x) {
        const int base = t * 256 + warp * 16;
        const int r0 = base + g, r1 = r0 + 8;
        const bool p0 = r0 < n, p1 = r1 < n;

        uint32_t a[4][4];
        #pragma unroll
        for (int kt = 0; kt < 4; kt++) {
            int c0 = kt * 16 + tk * 2;
            a[kt][0] = p0 ? *reinterpret_cast<const uint32_t*>(g_hy + (size_t)r0 * DD + c0) : 0u;
            a[kt][1] = p1 ? *reinterpret_cast<const uint32_t*>(g_hy + (size_t)r1 * DD + c0) : 0u;
            a[kt][2] = p0 ? *reinterpret_cast<const uint32_t*>(g_hy + (size_t)r0 * DD + c0 + 8) : 0u;
            a[kt][3] = p1 ? *reinterpret_cast<const uint32_t*>(g_hy + (size_t)r1 * DD + c0 + 8) : 0u;
        }
        const float dn0 = p0 ? g_dis[r0] : 0.f;
        const float dn1 = p1 ? g_dis[r1] : 0.f;

        #pragma unroll
        for (int nt = 0; nt < 8; nt++) {
            float d0 = 0.f, d1 = 0.f, d2 = 0.f, d3 = 0.f;
            #pragma unroll
            for (int kt = 0; kt < 4; kt++) {
                const __half* bp = &Wt[(nt * 8 + g) * WT_STRIDE + kt * 16 + tk * 2];
                uint32_t b0 = *reinterpret_cast<const uint32_t*>(bp);
                uint32_t b1 = *reinterpret_cast<const uint32_t*>(bp + 8);
                asm volatile(
                    "mma.sync.aligned.m16n8k16.row.col.f32.f16.f16.f32 "
                    "{%0,%1,%2,%3}, {%4,%5,%6,%7}, {%8,%9}, {%0,%1,%2,%3};"
                    : "+f"(d0), "+f"(d1), "+f"(d2), "+f"(d3)
                    : "r"(a[kt][0]), "r"(a[kt][1]), "r"(a[kt][2]), "r"(a[kt][3]),
                      "r"(b0), "r"(b1));
            }
            int col = nt * 8 + tk * 2;
            float2 bv = *reinterpret_cast<const float2*>(bias + col);
            float y00 = d0 + bv.x, y01 = d1 + bv.y;
            float y10 = d2 + bv.x, y11 = d3 + bv.y;
            if (last) {
                if (p0) *reinterpret_cast<float2*>(dout + (size_t)r0 * DD + col) = make_float2(y00, y01);
                if (p1) *reinterpret_cast<float2*>(dout + (size_t)r1 * DD + col) = make_float2(y10, y11);
            } else {
                if (p0) *reinterpret_cast<__half2*>(g_hx + (size_t)r0 * DD + col) =
                            __floats2half2_rn(dn0 * y00, dn0 * y01);
                if (p1) *reinterpret_cast<__half2*>(g_hx + (size_t)r1 * DD + col) =
                            __floats2half2_rn(dn1 * y10, dn1 * y11);
            }
        }
    }
}

// ---------------------------------------------------------------------------
extern "C" void kernel_launch(void* const* d_in, const int* in_sizes, int n_in,
                              void* d_out, int out_size) {
    const float* x  = (const float*)d_in[0];
    const int*   ei = (const int*)d_in[1];
    const float* W[3] = { (const float*)d_in[2], (const float*)d_in[4], (const float*)d_in[6] };
    const float* B[3] = { (const float*)d_in[3], (const float*)d_in[5], (const float*)d_in[7] };

    int n = in_sizes[0] / DD; if (n > NN) n = NN;
    int e = in_sizes[1] / 2;  if (e > EE) e = EE;
    const int* src = ei;
    const int* dst = ei + e;

    void* p = nullptr;
    cudaGetSymbolAddress(&p, g_cnt);
    cudaMemsetAsync(p, 0, (size_t)n * sizeof(int));
    cudaGetSymbolAddress(&p, g_state);
    cudaMemsetAsync(p, 0, 128 * sizeof(int));

    int nb = (n + 1023) / 1024;
    hist_k    <<<(e + 255) / 256, 256>>>(dst, e);      // kernel 1
    scan_all_k<<<nb, 1024>>>(x, n);                    // kernel 2
    scat_k    <<<(e + 255) / 256, 256>>>(src, dst, e); // kernel 3

    const int agg_grid = (n * 32 + 255) / 256;         // one warp per node

    agg_k <<<agg_grid, 256>>>(n);                      // kernel 4 <- profiled
    gemm_k<<<GEMM_BLOCKS, 512>>>(W[0], B[0], nullptr, 0, n);
    agg_k <<<agg_grid, 256>>>(n);
    gemm_k<<<GEMM_BLOCKS, 512>>>(W[1], B[1], nullptr, 0, n);
    agg_k <<<agg_grid, 256>>>(n);
    gemm_k<<<GEMM_BLOCKS, 512>>>(W[2], B[2], (float*)d_out, 1, n);
}